// round 3
// baseline (speedup 1.0000x reference)
#include <cuda_runtime.h>

#define NF    20480
#define NACC  128
#define BATCH 4096
#define REC   132          // 128 acc weights + 2 psqt + 2 pad (528B, 16B aligned)
#define RECV4 33           // REC/4

// Packed feature-major table: g_table[f*132 + s], s<128 -> acc_w[s][f],
// s==128/129 -> psqt_w[0/1][f], s==130/131 -> 0.
__device__ float g_table[(size_t)NF * REC];

// ---------------------------------------------------------------------------
// Kernel 1: tiled transpose acc_w [128,20480] + psqt_w [2,20480] into g_table.
// One block per 32 features. Coalesced reads (over f) and writes (over s).
// ---------------------------------------------------------------------------
__global__ __launch_bounds__(256) void build_table_kernel(
    const float* __restrict__ acc_w,
    const float* __restrict__ psqt_w)
{
    __shared__ float tile[32][133];   // pad 133: stride%32=5, conflict-free
    const int f0 = blockIdx.x * 32;

    for (int idx = threadIdx.x; idx < 32 * REC; idx += 256) {
        int s  = idx >> 5;            // 0..131
        int fl = idx & 31;
        int f  = f0 + fl;
        float v = 0.0f;
        if (s < NACC)      v = acc_w[(size_t)s * NF + f];
        else if (s == 128) v = psqt_w[f];
        else if (s == 129) v = psqt_w[NF + f];
        tile[fl][s] = v;
    }
    __syncthreads();
    for (int idx = threadIdx.x; idx < 32 * REC; idx += 256) {
        int fl = idx / REC;
        int s  = idx - fl * REC;
        g_table[(size_t)(f0 + fl) * REC + s] = tile[fl][s];
    }
}

// ---------------------------------------------------------------------------
// Kernel 2: one warp per batch row, processes white then black.
// Streaming scan of the row (512 floats / warp-iter, MLP=4, __ldcs),
// ballot-based sparse gather of table columns (L2-resident).
// ---------------------------------------------------------------------------
__global__ __launch_bounds__(256) void nnue_main_kernel(
    const float* __restrict__ white,
    const float* __restrict__ black,
    const float* __restrict__ acc_b,
    const float* __restrict__ out_w,
    float* __restrict__ out)
{
    const int warp = (blockIdx.x * blockDim.x + threadIdx.x) >> 5;
    const int lane = threadIdx.x & 31;
    if (warp >= BATCH) return;

    const float4* __restrict__ tbl = reinterpret_cast<const float4*>(g_table);
    const float4 bias = reinterpret_cast<const float4*>(acc_b)[lane];
    const float4 ow0  = reinterpret_cast<const float4*>(out_w)[lane];
    const float4 ow1  = reinterpret_cast<const float4*>(out_w)[32 + lane];

    float r0 = 0.0f, r1 = 0.0f;     // final (white - black) partials, lane 0

    #pragma unroll 1
    for (int side = 0; side < 2; ++side) {
        const float* base_ptr = (side == 0 ? white : black);
        const float4* __restrict__ row =
            reinterpret_cast<const float4*>(base_ptr + (size_t)warp * NF);

        // accumulator: lane holds features 4*lane .. 4*lane+3 (bias pre-added)
        float ax = bias.x, ay = bias.y, az = bias.z, aw = bias.w;
        float p0 = 0.0f, p1 = 0.0f;   // psqt partials, meaningful on lane 0

        // 20480 floats = 5120 float4 = 40 iters of 128 float4 per warp
        #pragma unroll 1
        for (int it = 0; it < NF / 512; ++it) {
            const int b4 = it * 128 + lane;     // float4 index of q0
            float4 q0 = __ldcs(row + b4);
            float4 q1 = __ldcs(row + b4 + 32);
            float4 q2 = __ldcs(row + b4 + 64);
            float4 q3 = __ldcs(row + b4 + 96);

            #pragma unroll
            for (int u = 0; u < 4; ++u) {
                float4 q = (u == 0) ? q0 : (u == 1) ? q1 : (u == 2) ? q2 : q3;
                unsigned any_m = __ballot_sync(0xffffffffu,
                    (q.x != 0.0f) | (q.y != 0.0f) | (q.z != 0.0f) | (q.w != 0.0f));
                if (any_m == 0u) continue;      // warp-uniform: common fast path

                #pragma unroll
                for (int k = 0; k < 4; ++k) {
                    float qc = (k == 0) ? q.x : (k == 1) ? q.y : (k == 2) ? q.z : q.w;
                    unsigned m = __ballot_sync(0xffffffffu, qc != 0.0f);
                    while (m) {
                        int src = __ffs(m) - 1;
                        m &= m - 1;
                        int j = 4 * (it * 128 + 32 * u + src) + k;  // feature id
                        float4 t = tbl[(size_t)j * RECV4 + lane];
                        ax += t.x; ay += t.y; az += t.z; aw += t.w;
                        if (lane == 0) {
                            float4 pq = tbl[(size_t)j * RECV4 + 32];
                            p0 += pq.x; p1 += pq.y;
                        }
                    }
                }
            }
        }

        // clip to [0,1]
        ax = fminf(fmaxf(ax, 0.0f), 1.0f);
        ay = fminf(fmaxf(ay, 0.0f), 1.0f);
        az = fminf(fmaxf(az, 0.0f), 1.0f);
        aw = fminf(fmaxf(aw, 0.0f), 1.0f);

        float s0 = ax * ow0.x + ay * ow0.y + az * ow0.z + aw * ow0.w;
        float s1 = ax * ow1.x + ay * ow1.y + az * ow1.z + aw * ow1.w;
        #pragma unroll
        for (int off = 16; off > 0; off >>= 1) {
            s0 += __shfl_xor_sync(0xffffffffu, s0, off);
            s1 += __shfl_xor_sync(0xffffffffu, s1, off);
        }

        const float sgn = (side == 0) ? 1.0f : -1.0f;
        if (lane == 0) {
            r0 += sgn * (p0 + s0);
            r1 += sgn * (p1 + s1);
        }
    }

    if (lane == 0) {
        reinterpret_cast<float2*>(out)[warp] = make_float2(r0, r1);
    }
}

// ---------------------------------------------------------------------------
extern "C" void kernel_launch(void* const* d_in, const int* in_sizes, int n_in,
                              void* d_out, int out_size)
{
    const float* white  = (const float*)d_in[0];
    const float* black  = (const float*)d_in[1];
    const float* psqt_w = (const float*)d_in[2];
    const float* acc_w  = (const float*)d_in[3];
    const float* acc_b  = (const float*)d_in[4];
    const float* out_w  = (const float*)d_in[5];
    (void)in_sizes; (void)n_in; (void)out_size;

    build_table_kernel<<<NF / 32, 256>>>(acc_w, psqt_w);
    nnue_main_kernel<<<BATCH / 8, 256>>>(white, black, acc_b, out_w,
                                         (float*)d_out);
}

// round 5
// speedup vs baseline: 1.0128x; 1.0128x over previous
#include <cuda_runtime.h>

#define NF    20480
#define NACC  128
#define BATCH 4096
#define REC   132          // 128 acc weights + 2 psqt + 2 pad (528B, 16B aligned)
#define RECV4 33           // REC/4
#define HALF4 (NF / 2 / 4) // 2560 float4 per half-row
#define ITERS (NF / 2 / 512) // 20 iterations of 512 floats per half

// Packed feature-major table: g_table[f*132 + s], s<128 -> acc_w[s][f],
// s==128/129 -> psqt_w[0/1][f], s==130/131 -> 0.
__device__ float g_table[(size_t)NF * REC];

// ---------------------------------------------------------------------------
// Kernel 1: tiled transpose acc_w [128,20480] + psqt_w [2,20480] into g_table.
// ---------------------------------------------------------------------------
__global__ __launch_bounds__(256) void build_table_kernel(
    const float* __restrict__ acc_w,
    const float* __restrict__ psqt_w)
{
    __shared__ float tile[32][133];
    const int f0 = blockIdx.x * 32;

    for (int idx = threadIdx.x; idx < 32 * REC; idx += 256) {
        int s  = idx >> 5;
        int fl = idx & 31;
        int f  = f0 + fl;
        float v = 0.0f;
        if (s < NACC)      v = acc_w[(size_t)s * NF + f];
        else if (s == 128) v = psqt_w[f];
        else if (s == 129) v = psqt_w[NF + f];
        tile[fl][s] = v;
    }
    __syncthreads();
    for (int idx = threadIdx.x; idx < 32 * REC; idx += 256) {
        int fl = idx / REC;
        int s  = idx - fl * REC;
        g_table[(size_t)(f0 + fl) * REC + s] = tile[fl][s];
    }
}

// ---------------------------------------------------------------------------
// Kernel 2: 8 warps per block = 2 rows x 2 sides x 2 feature-halves.
// Each warp streams 10240 floats (20 iters x 512) of one (row, side, half),
// gathers active table columns (L2-resident), then halves/sides merge in smem.
// ---------------------------------------------------------------------------
__global__ __launch_bounds__(256) void nnue_main_kernel(
    const float* __restrict__ white,
    const float* __restrict__ black,
    const float* __restrict__ acc_b,
    const float* __restrict__ out_w,
    float* __restrict__ out)
{
    const int tid  = threadIdx.x;
    const int w    = tid >> 5;          // 0..7
    const int lane = tid & 31;
    const int rl   = w >> 2;            // row within block: 0..1
    const int side = (w >> 1) & 1;      // 0=white, 1=black
    const int half = w & 1;             // feature half
    const int row  = blockIdx.x * 2 + rl;

    __shared__ float s_acc[2][2][NACC];   // [row_local][side][128]
    __shared__ float s_ps[2][2][2];       // half=1 psqt partials
    __shared__ float s_res[2][2][2];      // per-side results

    const float4* __restrict__ tbl = reinterpret_cast<const float4*>(g_table);
    const float* base_ptr = (side == 0 ? white : black);
    const float4* __restrict__ rowp =
        reinterpret_cast<const float4*>(base_ptr + (size_t)row * NF) + half * HALF4;

    // accumulator: lane holds features 4*lane .. 4*lane+3; bias only in half 0
    float ax, ay, az, aw;
    if (half == 0) {
        float4 b = reinterpret_cast<const float4*>(acc_b)[lane];
        ax = b.x; ay = b.y; az = b.z; aw = b.w;
    } else {
        ax = ay = az = aw = 0.0f;
    }
    float p0 = 0.0f, p1 = 0.0f;           // psqt partials (lane 0)
    const int fbase4 = half * HALF4;      // float4 offset of this half

    #pragma unroll 1
    for (int it = 0; it < ITERS; ++it) {
        const int b4 = it * 128 + lane;
        float4 q0 = __ldcs(rowp + b4);
        float4 q1 = __ldcs(rowp + b4 + 32);
        float4 q2 = __ldcs(rowp + b4 + 64);
        float4 q3 = __ldcs(rowp + b4 + 96);

        #pragma unroll
        for (int u = 0; u < 4; ++u) {
            float4 q = (u == 0) ? q0 : (u == 1) ? q1 : (u == 2) ? q2 : q3;
            unsigned any_m = __ballot_sync(0xffffffffu,
                (q.x != 0.0f) | (q.y != 0.0f) | (q.z != 0.0f) | (q.w != 0.0f));
            if (any_m == 0u) continue;      // warp-uniform: common fast path

            #pragma unroll
            for (int k = 0; k < 4; ++k) {
                float qc = (k == 0) ? q.x : (k == 1) ? q.y : (k == 2) ? q.z : q.w;
                unsigned m = __ballot_sync(0xffffffffu, qc != 0.0f);
                while (m) {
                    int src = __ffs(m) - 1;
                    m &= m - 1;
                    int j = 4 * (fbase4 + it * 128 + 32 * u + src) + k;
                    float4 t = tbl[(size_t)j * RECV4 + lane];
                    ax += t.x; ay += t.y; az += t.z; aw += t.w;
                    if (lane == 0) {
                        float4 pq = tbl[(size_t)j * RECV4 + 32];
                        p0 += pq.x; p1 += pq.y;
                    }
                }
            }
        }
    }

    // ---- merge the two feature-halves (must happen BEFORE clip) ----
    if (half == 1) {
        s_acc[rl][side][4 * lane + 0] = ax;
        s_acc[rl][side][4 * lane + 1] = ay;
        s_acc[rl][side][4 * lane + 2] = az;
        s_acc[rl][side][4 * lane + 3] = aw;
        if (lane == 0) { s_ps[rl][side][0] = p0; s_ps[rl][side][1] = p1; }
    }
    __syncthreads();

    if (half == 0) {
        ax += s_acc[rl][side][4 * lane + 0];
        ay += s_acc[rl][side][4 * lane + 1];
        az += s_acc[rl][side][4 * lane + 2];
        aw += s_acc[rl][side][4 * lane + 3];

        ax = fminf(fmaxf(ax, 0.0f), 1.0f);
        ay = fminf(fmaxf(ay, 0.0f), 1.0f);
        az = fminf(fmaxf(az, 0.0f), 1.0f);
        aw = fminf(fmaxf(aw, 0.0f), 1.0f);

        const float4 ow0 = reinterpret_cast<const float4*>(out_w)[lane];
        const float4 ow1 = reinterpret_cast<const float4*>(out_w)[32 + lane];
        float s0 = ax * ow0.x + ay * ow0.y + az * ow0.z + aw * ow0.w;
        float s1 = ax * ow1.x + ay * ow1.y + az * ow1.z + aw * ow1.w;
        #pragma unroll
        for (int off = 16; off > 0; off >>= 1) {
            s0 += __shfl_xor_sync(0xffffffffu, s0, off);
            s1 += __shfl_xor_sync(0xffffffffu, s1, off);
        }
        if (lane == 0) {
            s_res[rl][side][0] = p0 + s_ps[rl][side][0] + s0;
            s_res[rl][side][1] = p1 + s_ps[rl][side][1] + s1;
        }
    }
    __syncthreads();

    // ---- white - black, one thread per row ----
    if (tid < 2) {
        float2 r;
        r.x = s_res[tid][0][0] - s_res[tid][1][0];
        r.y = s_res[tid][0][1] - s_res[tid][1][1];
        reinterpret_cast<float2*>(out)[blockIdx.x * 2 + tid] = r;
    }
}

// ---------------------------------------------------------------------------
extern "C" void kernel_launch(void* const* d_in, const int* in_sizes, int n_in,
                              void* d_out, int out_size)
{
    const float* white  = (const float*)d_in[0];
    const float* black  = (const float*)d_in[1];
    const float* psqt_w = (const float*)d_in[2];
    const float* acc_w  = (const float*)d_in[3];
    const float* acc_b  = (const float*)d_in[4];
    const float* out_w  = (const float*)d_in[5];
    (void)in_sizes; (void)n_in; (void)out_size;

    build_table_kernel<<<NF / 32, 256>>>(acc_w, psqt_w);
    nnue_main_kernel<<<BATCH / 2, 256>>>(white, black, acc_b, out_w,
                                         (float*)d_out);
}

// round 6
// speedup vs baseline: 1.0328x; 1.0198x over previous
#include <cuda_runtime.h>

#define NF    20480
#define NACC  128
#define BATCH 4096
#define REC   132            // 128 acc weights + 2 psqt + 2 pad (528B, 16B aligned)
#define RECV4 33             // REC/4
#define QTR4  (NF / 4 / 4)   // 1280 float4 per quarter-row
#define ITERS (NF / 4 / 512) // 10 iterations of 512 floats per quarter

// Packed feature-major table: g_table[f*132 + s], s<128 -> acc_w[s][f],
// s==128/129 -> psqt_w[0/1][f], s==130/131 -> 0.
__device__ float g_table[(size_t)NF * REC];

// ---------------------------------------------------------------------------
// Kernel 1: tiled transpose acc_w [128,20480] + psqt_w [2,20480] into g_table.
// ---------------------------------------------------------------------------
__global__ __launch_bounds__(256) void build_table_kernel(
    const float* __restrict__ acc_w,
    const float* __restrict__ psqt_w)
{
    __shared__ float tile[32][133];
    const int f0 = blockIdx.x * 32;

    for (int idx = threadIdx.x; idx < 32 * REC; idx += 256) {
        int s  = idx >> 5;
        int fl = idx & 31;
        int f  = f0 + fl;
        float v = 0.0f;
        if (s < NACC)      v = acc_w[(size_t)s * NF + f];
        else if (s == 128) v = psqt_w[f];
        else if (s == 129) v = psqt_w[NF + f];
        tile[fl][s] = v;
    }
    __syncthreads();
    for (int idx = threadIdx.x; idx < 32 * REC; idx += 256) {
        int fl = idx / REC;
        int s  = idx - fl * REC;
        g_table[(size_t)(f0 + fl) * REC + s] = tile[fl][s];
    }
}

// ---------------------------------------------------------------------------
// Kernel 2: 8 warps per block = 1 row x 2 sides x 4 feature-quarters.
// PDL: streaming prologue loads issue before cudaGridDependencySynchronize(),
// overlapping with build_table_kernel. Per-warp double-buffered streaming.
// ---------------------------------------------------------------------------
__global__ __launch_bounds__(256) void nnue_main_kernel(
    const float* __restrict__ white,
    const float* __restrict__ black,
    const float* __restrict__ acc_b,
    const float* __restrict__ out_w,
    float* __restrict__ out)
{
    const int tid  = threadIdx.x;
    const int w    = tid >> 5;          // 0..7
    const int lane = tid & 31;
    const int side = w >> 2;            // 0=white, 1=black
    const int q    = w & 3;             // feature quarter
    const int row  = blockIdx.x;

    __shared__ float s_acc[2][4][NACC]; // [side][quarter][128]
    __shared__ float s_ps[2][4][2];     // psqt partials
    __shared__ float s_res[2][2];       // per-side results

    const float4* __restrict__ tbl = reinterpret_cast<const float4*>(g_table);
    const float* base_ptr = (side == 0 ? white : black);
    const float4* __restrict__ rowp =
        reinterpret_cast<const float4*>(base_ptr + (size_t)row * NF) + q * QTR4;
    const int fbase4 = q * QTR4;

    // accumulator: lane holds features 4*lane .. 4*lane+3; bias only in q==0
    float ax, ay, az, aw;
    if (q == 0) {
        float4 b = reinterpret_cast<const float4*>(acc_b)[lane];
        ax = b.x; ay = b.y; az = b.z; aw = b.w;
    } else {
        ax = ay = az = aw = 0.0f;
    }
    float p0 = 0.0f, p1 = 0.0f;

    // ---- prologue: issue iter-0 streaming loads BEFORE waiting on builder ----
    float4 q0 = __ldcs(rowp + lane);
    float4 q1 = __ldcs(rowp + lane + 32);
    float4 q2 = __ldcs(rowp + lane + 64);
    float4 q3 = __ldcs(rowp + lane + 96);

    cudaGridDependencySynchronize();    // table is valid after this point

    #pragma unroll 1
    for (int it = 0; it < ITERS; ++it) {
        // prefetch next iteration's stream while we process this one
        float4 n0, n1, n2, n3;
        if (it + 1 < ITERS) {
            const int b4 = (it + 1) * 128 + lane;
            n0 = __ldcs(rowp + b4);
            n1 = __ldcs(rowp + b4 + 32);
            n2 = __ldcs(rowp + b4 + 64);
            n3 = __ldcs(rowp + b4 + 96);
        }

        #pragma unroll
        for (int u = 0; u < 4; ++u) {
            float4 qq = (u == 0) ? q0 : (u == 1) ? q1 : (u == 2) ? q2 : q3;
            unsigned any_m = __ballot_sync(0xffffffffu,
                (qq.x != 0.0f) | (qq.y != 0.0f) | (qq.z != 0.0f) | (qq.w != 0.0f));
            if (any_m == 0u) continue;      // warp-uniform: common fast path

            #pragma unroll
            for (int k = 0; k < 4; ++k) {
                float qc = (k == 0) ? qq.x : (k == 1) ? qq.y : (k == 2) ? qq.z : qq.w;
                unsigned m = __ballot_sync(0xffffffffu, qc != 0.0f);
                while (m) {
                    int src = __ffs(m) - 1;
                    m &= m - 1;
                    int j = 4 * (fbase4 + it * 128 + 32 * u + src) + k;
                    float4 t = tbl[(size_t)j * RECV4 + lane];
                    ax += t.x; ay += t.y; az += t.z; aw += t.w;
                    if (lane == 0) {
                        float4 pq = tbl[(size_t)j * RECV4 + 32];
                        p0 += pq.x; p1 += pq.y;
                    }
                }
            }
        }
        q0 = n0; q1 = n1; q2 = n2; q3 = n3;
    }

    // ---- publish partial accumulators (merge BEFORE clip) ----
    reinterpret_cast<float4*>(&s_acc[side][q][0])[lane] =
        make_float4(ax, ay, az, aw);
    if (lane == 0) { s_ps[side][q][0] = p0; s_ps[side][q][1] = p1; }
    __syncthreads();

    // ---- one warp per side reduces 4 quarters, clips, applies output layer ----
    if (q == 0) {
        float4 a0 = reinterpret_cast<const float4*>(&s_acc[side][0][0])[lane];
        float4 a1 = reinterpret_cast<const float4*>(&s_acc[side][1][0])[lane];
        float4 a2 = reinterpret_cast<const float4*>(&s_acc[side][2][0])[lane];
        float4 a3 = reinterpret_cast<const float4*>(&s_acc[side][3][0])[lane];
        float rx = a0.x + a1.x + a2.x + a3.x;
        float ry = a0.y + a1.y + a2.y + a3.y;
        float rz = a0.z + a1.z + a2.z + a3.z;
        float rw = a0.w + a1.w + a2.w + a3.w;

        rx = fminf(fmaxf(rx, 0.0f), 1.0f);
        ry = fminf(fmaxf(ry, 0.0f), 1.0f);
        rz = fminf(fmaxf(rz, 0.0f), 1.0f);
        rw = fminf(fmaxf(rw, 0.0f), 1.0f);

        const float4 ow0 = reinterpret_cast<const float4*>(out_w)[lane];
        const float4 ow1 = reinterpret_cast<const float4*>(out_w)[32 + lane];
        float s0 = rx * ow0.x + ry * ow0.y + rz * ow0.z + rw * ow0.w;
        float s1 = rx * ow1.x + ry * ow1.y + rz * ow1.z + rw * ow1.w;
        #pragma unroll
        for (int off = 16; off > 0; off >>= 1) {
            s0 += __shfl_xor_sync(0xffffffffu, s0, off);
            s1 += __shfl_xor_sync(0xffffffffu, s1, off);
        }
        if (lane == 0) {
            float pp0 = s_ps[side][0][0] + s_ps[side][1][0]
                      + s_ps[side][2][0] + s_ps[side][3][0];
            float pp1 = s_ps[side][0][1] + s_ps[side][1][1]
                      + s_ps[side][2][1] + s_ps[side][3][1];
            s_res[side][0] = pp0 + s0;
            s_res[side][1] = pp1 + s1;
        }
    }
    __syncthreads();

    if (tid == 0) {
        float2 r;
        r.x = s_res[0][0] - s_res[1][0];
        r.y = s_res[0][1] - s_res[1][1];
        reinterpret_cast<float2*>(out)[row] = r;
    }
}

// ---------------------------------------------------------------------------
extern "C" void kernel_launch(void* const* d_in, const int* in_sizes, int n_in,
                              void* d_out, int out_size)
{
    const float* white  = (const float*)d_in[0];
    const float* black  = (const float*)d_in[1];
    const float* psqt_w = (const float*)d_in[2];
    const float* acc_w  = (const float*)d_in[3];
    const float* acc_b  = (const float*)d_in[4];
    const float* out_w  = (const float*)d_in[5];
    (void)in_sizes; (void)n_in; (void)out_size;

    build_table_kernel<<<NF / 32, 256>>>(acc_w, psqt_w);

    // PDL launch: main kernel co-launches with builder; each thread issues its
    // first streaming loads, then blocks at cudaGridDependencySynchronize()
    // until build_table_kernel completes.
    cudaLaunchConfig_t cfg = {};
    cfg.gridDim  = dim3(BATCH);
    cfg.blockDim = dim3(256);
    cfg.dynamicSmemBytes = 0;
    cfg.stream = 0;
    cudaLaunchAttribute attrs[1];
    attrs[0].id = cudaLaunchAttributeProgrammaticStreamSerialization;
    attrs[0].val.programmaticStreamSerializationAllowed = 1;
    cfg.attrs = attrs;
    cfg.numAttrs = 1;
    cudaLaunchKernelEx(&cfg, nnue_main_kernel,
                       white, black, acc_b, out_w, (float*)d_out);
}

// round 7
// speedup vs baseline: 1.1318x; 1.0958x over previous
#include <cuda_runtime.h>

#define NF    20480
#define NACC  128
#define BATCH 4096
#define REC   132            // 128 acc weights + 2 psqt + 2 pad (528B, 16B aligned)
#define RECV4 33             // REC/4
#define QTR4  (NF / 4 / 4)   // 1280 float4 per quarter-row
#define ITERS (NF / 4 / 512) // 10 iterations of 512 floats per quarter
#define CAP   128            // per-warp active-feature list capacity
#define FULLM 0xffffffffu

// Packed feature-major table: g_table[f*132 + s], s<128 -> acc_w[s][f],
// s==128/129 -> psqt_w[0/1][f], s==130/131 -> 0.
__device__ float g_table[(size_t)NF * REC];

// ---------------------------------------------------------------------------
// Kernel 1: tiled transpose acc_w [128,20480] + psqt_w [2,20480] into g_table.
// Triggers PDL completion at entry so the main kernel co-schedules and runs
// its (table-independent) streaming phase concurrently.
// ---------------------------------------------------------------------------
__global__ __launch_bounds__(256) void build_table_kernel(
    const float* __restrict__ acc_w,
    const float* __restrict__ psqt_w)
{
    cudaTriggerProgrammaticLaunchCompletion();

    __shared__ float tile[32][133];
    const int f0 = blockIdx.x * 32;

    for (int idx = threadIdx.x; idx < 32 * REC; idx += 256) {
        int s  = idx >> 5;
        int fl = idx & 31;
        int f  = f0 + fl;
        float v = 0.0f;
        if (s < NACC)      v = acc_w[(size_t)s * NF + f];
        else if (s == 128) v = psqt_w[f];
        else if (s == 129) v = psqt_w[NF + f];
        tile[fl][s] = v;
    }
    __syncthreads();
    for (int idx = threadIdx.x; idx < 32 * REC; idx += 256) {
        int fl = idx / REC;
        int s  = idx - fl * REC;
        g_table[(size_t)(f0 + fl) * REC + s] = tile[fl][s];
    }
}

// ---------------------------------------------------------------------------
// Kernel 2: 8 warps per block = 1 row x 2 sides x 4 feature-quarters.
// Phase 1: pure streaming scan -> active-index list in smem (no table access,
//          so DRAM requests are never stalled behind L2 gather chains).
// Grid sync (builder guaranteed done by now; overlapped via PDL trigger).
// Phase 2: batched L2 gather over the index list.
// ---------------------------------------------------------------------------
__global__ __launch_bounds__(256) void nnue_main_kernel(
    const float* __restrict__ white,
    const float* __restrict__ black,
    const float* __restrict__ acc_b,
    const float* __restrict__ out_w,
    float* __restrict__ out)
{
    const int tid  = threadIdx.x;
    const int w    = tid >> 5;          // 0..7
    const int lane = tid & 31;
    const int side = w >> 2;            // 0=white, 1=black
    const int q    = w & 3;             // feature quarter
    const int row  = blockIdx.x;

    __shared__ int   s_idx[8][CAP];     // per-warp active feature ids
    __shared__ float s_acc[2][4][NACC]; // [side][quarter][128]
    __shared__ float s_ps[2][4][2];     // psqt partials
    __shared__ float s_res[2][2];       // per-side results

    const float* base_ptr = (side == 0 ? white : black);
    const float4* __restrict__ rowp =
        reinterpret_cast<const float4*>(base_ptr + (size_t)row * NF) + q * QTR4;
    const int fbase4 = q * QTR4;

    // ================= Phase 1: streaming scan =================
    int cnt = 0;                        // warp-uniform

    float4 q0 = __ldcs(rowp + lane);
    float4 q1 = __ldcs(rowp + lane + 32);
    float4 q2 = __ldcs(rowp + lane + 64);
    float4 q3 = __ldcs(rowp + lane + 96);

    #pragma unroll 1
    for (int it = 0; it < ITERS; ++it) {
        float4 n0, n1, n2, n3;
        if (it + 1 < ITERS) {
            const int b4 = (it + 1) * 128 + lane;
            n0 = __ldcs(rowp + b4);
            n1 = __ldcs(rowp + b4 + 32);
            n2 = __ldcs(rowp + b4 + 64);
            n3 = __ldcs(rowp + b4 + 96);
        }

        #pragma unroll
        for (int u = 0; u < 4; ++u) {
            float4 qq = (u == 0) ? q0 : (u == 1) ? q1 : (u == 2) ? q2 : q3;
            unsigned mask4 = (unsigned)(qq.x != 0.0f)
                           | ((unsigned)(qq.y != 0.0f) << 1)
                           | ((unsigned)(qq.z != 0.0f) << 2)
                           | ((unsigned)(qq.w != 0.0f) << 3);
            unsigned any_m = __ballot_sync(FULLM, mask4 != 0u);
            while (any_m) {                     // warp-uniform loop
                int src = __ffs(any_m) - 1;
                any_m &= any_m - 1;
                unsigned m4 = __shfl_sync(FULLM, mask4, src);
                int bj = 4 * (fbase4 + it * 128 + 32 * u + src);
                while (m4) {
                    int c = __ffs(m4) - 1;
                    m4 &= m4 - 1;
                    if (lane == 0 && cnt < CAP) s_idx[w][cnt] = bj + c;
                    ++cnt;
                }
            }
        }
        q0 = n0; q1 = n1; q2 = n2; q3 = n3;
    }
    if (cnt > CAP) cnt = CAP;
    __syncwarp();                        // make s_idx visible to whole warp

    // builder finished long ago (PDL overlap); this returns immediately
    cudaGridDependencySynchronize();

    // ================= Phase 2: batched gather =================
    const float4* __restrict__ tbl = reinterpret_cast<const float4*>(g_table);

    float ax, ay, az, aw;
    if (q == 0) {
        float4 b = reinterpret_cast<const float4*>(acc_b)[lane];
        ax = b.x; ay = b.y; az = b.z; aw = b.w;
    } else {
        ax = ay = az = aw = 0.0f;
    }
    float p0 = 0.0f, p1 = 0.0f;          // psqt partials (lanes 0 and 1)

    int i = 0;
    #pragma unroll 1
    for (; i + 2 <= cnt; i += 2) {       // two independent L2 loads in flight
        int j0 = s_idx[w][i];
        int j1 = s_idx[w][i + 1];
        float4 t0 = tbl[(size_t)j0 * RECV4 + lane];
        float4 t1 = tbl[(size_t)j1 * RECV4 + lane];
        if (lane < 2) {                  // lane0 -> j0 psqt, lane1 -> j1 psqt
            int jp = (lane == 0) ? j0 : j1;
            float4 pq = tbl[(size_t)jp * RECV4 + 32];
            p0 += pq.x; p1 += pq.y;
        }
        ax += t0.x; ay += t0.y; az += t0.z; aw += t0.w;
        ax += t1.x; ay += t1.y; az += t1.z; aw += t1.w;
    }
    if (i < cnt) {
        int j0 = s_idx[w][i];
        float4 t0 = tbl[(size_t)j0 * RECV4 + lane];
        if (lane == 0) {
            float4 pq = tbl[(size_t)j0 * RECV4 + 32];
            p0 += pq.x; p1 += pq.y;
        }
        ax += t0.x; ay += t0.y; az += t0.z; aw += t0.w;
    }
    // reduce psqt partials (live in lanes 0/1) across the warp
    #pragma unroll
    for (int off = 16; off > 0; off >>= 1) {
        p0 += __shfl_xor_sync(FULLM, p0, off);
        p1 += __shfl_xor_sync(FULLM, p1, off);
    }

    // ---- publish partial accumulators (merge BEFORE clip) ----
    reinterpret_cast<float4*>(&s_acc[side][q][0])[lane] =
        make_float4(ax, ay, az, aw);
    if (lane == 0) { s_ps[side][q][0] = p0; s_ps[side][q][1] = p1; }
    __syncthreads();

    // ---- one warp per side reduces 4 quarters, clips, applies output layer ----
    if (q == 0) {
        float4 a0 = reinterpret_cast<const float4*>(&s_acc[side][0][0])[lane];
        float4 a1 = reinterpret_cast<const float4*>(&s_acc[side][1][0])[lane];
        float4 a2 = reinterpret_cast<const float4*>(&s_acc[side][2][0])[lane];
        float4 a3 = reinterpret_cast<const float4*>(&s_acc[side][3][0])[lane];
        float rx = a0.x + a1.x + a2.x + a3.x;
        float ry = a0.y + a1.y + a2.y + a3.y;
        float rz = a0.z + a1.z + a2.z + a3.z;
        float rw = a0.w + a1.w + a2.w + a3.w;

        rx = fminf(fmaxf(rx, 0.0f), 1.0f);
        ry = fminf(fmaxf(ry, 0.0f), 1.0f);
        rz = fminf(fmaxf(rz, 0.0f), 1.0f);
        rw = fminf(fmaxf(rw, 0.0f), 1.0f);

        const float4 ow0 = reinterpret_cast<const float4*>(out_w)[lane];
        const float4 ow1 = reinterpret_cast<const float4*>(out_w)[32 + lane];
        float s0 = rx * ow0.x + ry * ow0.y + rz * ow0.z + rw * ow0.w;
        float s1 = rx * ow1.x + ry * ow1.y + rz * ow1.z + rw * ow1.w;
        #pragma unroll
        for (int off = 16; off > 0; off >>= 1) {
            s0 += __shfl_xor_sync(FULLM, s0, off);
            s1 += __shfl_xor_sync(FULLM, s1, off);
        }
        if (lane == 0) {
            float pp0 = s_ps[side][0][0] + s_ps[side][1][0]
                      + s_ps[side][2][0] + s_ps[side][3][0];
            float pp1 = s_ps[side][0][1] + s_ps[side][1][1]
                      + s_ps[side][2][1] + s_ps[side][3][1];
            s_res[side][0] = pp0 + s0;
            s_res[side][1] = pp1 + s1;
        }
    }
    __syncthreads();

    if (tid == 0) {
        float2 r;
        r.x = s_res[0][0] - s_res[1][0];
        r.y = s_res[0][1] - s_res[1][1];
        reinterpret_cast<float2*>(out)[row] = r;
    }
}

// ---------------------------------------------------------------------------
extern "C" void kernel_launch(void* const* d_in, const int* in_sizes, int n_in,
                              void* d_out, int out_size)
{
    const float* white  = (const float*)d_in[0];
    const float* black  = (const float*)d_in[1];
    const float* psqt_w = (const float*)d_in[2];
    const float* acc_w  = (const float*)d_in[3];
    const float* acc_b  = (const float*)d_in[4];
    const float* out_w  = (const float*)d_in[5];
    (void)in_sizes; (void)n_in; (void)out_size;

    build_table_kernel<<<NF / 32, 256>>>(acc_w, psqt_w);

    // PDL launch: builder triggers at entry, so the main kernel co-schedules
    // and streams inputs while the builder writes g_table; the grid sync at
    // the end of phase 1 guarantees table visibility.
    cudaLaunchConfig_t cfg = {};
    cfg.gridDim  = dim3(BATCH);
    cfg.blockDim = dim3(256);
    cfg.dynamicSmemBytes = 0;
    cfg.stream = 0;
    cudaLaunchAttribute attrs[1];
    attrs[0].id = cudaLaunchAttributeProgrammaticStreamSerialization;
    attrs[0].val.programmaticStreamSerializationAllowed = 1;
    cfg.attrs = attrs;
    cfg.numAttrs = 1;
    cudaLaunchKernelEx(&cfg, nnue_main_kernel,
                       white, black, acc_b, out_w, (float*)d_out);
}

// round 8
// speedup vs baseline: 1.1346x; 1.0025x over previous
#include <cuda_runtime.h>

#define NF    20480
#define NACC  128
#define BATCH 4096
#define REC   132            // 128 acc weights + 2 psqt + 2 pad (528B, 16B aligned)
#define RECV4 33             // REC/4
#define QTR4  (NF / 4 / 4)   // 1280 float4 per quarter-row
#define ITERS (NF / 4 / 512) // 10 iterations of 512 floats per quarter
#define CAP   96             // per-warp active-feature list capacity
#define FULLM 0xffffffffu

// Packed feature-major table: g_table[f*132 + s], s<128 -> acc_w[s][f],
// s==128/129 -> psqt_w[0/1][f], s==130/131 -> 0.
__device__ float g_table[(size_t)NF * REC];

// ---------------------------------------------------------------------------
// Kernel 1: tiled transpose acc_w [128,20480] + psqt_w [2,20480] into g_table.
// Also zeroes the output buffer (main kernel combines sides via atomicAdd).
// Triggers PDL completion at entry so the main kernel co-schedules and runs
// its (table-independent) streaming phase concurrently.
// ---------------------------------------------------------------------------
__global__ __launch_bounds__(256) void build_table_kernel(
    const float* __restrict__ acc_w,
    const float* __restrict__ psqt_w,
    float* __restrict__ out)
{
    cudaTriggerProgrammaticLaunchCompletion();

    // zero the 4096x2 output (poisoned by harness); 32 blocks x 256 threads
    if (blockIdx.x < 32) {
        out[blockIdx.x * 256 + threadIdx.x] = 0.0f;
    }

    __shared__ float tile[32][133];
    const int f0 = blockIdx.x * 32;

    for (int idx = threadIdx.x; idx < 32 * REC; idx += 256) {
        int s  = idx >> 5;
        int fl = idx & 31;
        int f  = f0 + fl;
        float v = 0.0f;
        if (s < NACC)      v = acc_w[(size_t)s * NF + f];
        else if (s == 128) v = psqt_w[f];
        else if (s == 129) v = psqt_w[NF + f];
        tile[fl][s] = v;
    }
    __syncthreads();
    for (int idx = threadIdx.x; idx < 32 * REC; idx += 256) {
        int fl = idx / REC;
        int s  = idx - fl * REC;
        g_table[(size_t)(f0 + fl) * REC + s] = tile[fl][s];
    }
}

// ---------------------------------------------------------------------------
// Kernel 2: block = (row, side), 128 threads = 4 warps, one feature-quarter
// per warp. Phase 1: pure streaming scan -> active-index list in smem.
// Grid sync (builder overlapped via PDL trigger). Phase 2: batched L2 gather,
// in-block quarter merge, clip + output layer, atomicAdd(+/-) into out[row].
// ---------------------------------------------------------------------------
__global__ __launch_bounds__(128, 12) void nnue_main_kernel(
    const float* __restrict__ white,
    const float* __restrict__ black,
    const float* __restrict__ acc_b,
    const float* __restrict__ out_w,
    float* __restrict__ out)
{
    const int tid  = threadIdx.x;
    const int q    = tid >> 5;          // warp = feature quarter, 0..3
    const int lane = tid & 31;
    const int side = blockIdx.x & 1;    // 0=white, 1=black
    const int row  = blockIdx.x >> 1;

    __shared__ int   s_idx[4][CAP];     // per-warp active feature ids
    __shared__ float s_acc[4][NACC];    // per-quarter partial accumulators
    __shared__ float s_ps[4][2];        // psqt partials

    const float* base_ptr = (side == 0 ? white : black);
    const float4* __restrict__ rowp =
        reinterpret_cast<const float4*>(base_ptr + (size_t)row * NF) + q * QTR4;
    const int fbase4 = q * QTR4;

    // ================= Phase 1: streaming scan =================
    int cnt = 0;                        // warp-uniform

    float4 q0 = __ldcs(rowp + lane);
    float4 q1 = __ldcs(rowp + lane + 32);
    float4 q2 = __ldcs(rowp + lane + 64);
    float4 q3 = __ldcs(rowp + lane + 96);

    #pragma unroll 1
    for (int it = 0; it < ITERS; ++it) {
        float4 n0, n1, n2, n3;
        if (it + 1 < ITERS) {
            const int b4 = (it + 1) * 128 + lane;
            n0 = __ldcs(rowp + b4);
            n1 = __ldcs(rowp + b4 + 32);
            n2 = __ldcs(rowp + b4 + 64);
            n3 = __ldcs(rowp + b4 + 96);
        }

        #pragma unroll
        for (int u = 0; u < 4; ++u) {
            float4 qq = (u == 0) ? q0 : (u == 1) ? q1 : (u == 2) ? q2 : q3;
            unsigned mask4 = (unsigned)(qq.x != 0.0f)
                           | ((unsigned)(qq.y != 0.0f) << 1)
                           | ((unsigned)(qq.z != 0.0f) << 2)
                           | ((unsigned)(qq.w != 0.0f) << 3);
            unsigned any_m = __ballot_sync(FULLM, mask4 != 0u);
            while (any_m) {                     // warp-uniform loop
                int src = __ffs(any_m) - 1;
                any_m &= any_m - 1;
                unsigned m4 = __shfl_sync(FULLM, mask4, src);
                int bj = 4 * (fbase4 + it * 128 + 32 * u + src);
                while (m4) {
                    int c = __ffs(m4) - 1;
                    m4 &= m4 - 1;
                    if (lane == 0 && cnt < CAP) s_idx[q][cnt] = bj + c;
                    ++cnt;
                }
            }
        }
        q0 = n0; q1 = n1; q2 = n2; q3 = n3;
    }
    if (cnt > CAP) cnt = CAP;
    __syncwarp();                        // make s_idx visible to whole warp

    // builder finished long ago (PDL overlap); this returns immediately
    cudaGridDependencySynchronize();

    // ================= Phase 2: batched gather =================
    const float4* __restrict__ tbl = reinterpret_cast<const float4*>(g_table);

    float ax, ay, az, aw;
    if (q == 0) {
        float4 b = reinterpret_cast<const float4*>(acc_b)[lane];
        ax = b.x; ay = b.y; az = b.z; aw = b.w;
    } else {
        ax = ay = az = aw = 0.0f;
    }
    float p0 = 0.0f, p1 = 0.0f;          // psqt partials (lanes 0 and 1)

    int i = 0;
    #pragma unroll 1
    for (; i + 2 <= cnt; i += 2) {       // two independent L2 loads in flight
        int j0 = s_idx[q][i];
        int j1 = s_idx[q][i + 1];
        float4 t0 = tbl[(size_t)j0 * RECV4 + lane];
        float4 t1 = tbl[(size_t)j1 * RECV4 + lane];
        if (lane < 2) {                  // lane0 -> j0 psqt, lane1 -> j1 psqt
            int jp = (lane == 0) ? j0 : j1;
            float4 pq = tbl[(size_t)jp * RECV4 + 32];
            p0 += pq.x; p1 += pq.y;
        }
        ax += t0.x; ay += t0.y; az += t0.z; aw += t0.w;
        ax += t1.x; ay += t1.y; az += t1.z; aw += t1.w;
    }
    if (i < cnt) {
        int j0 = s_idx[q][i];
        float4 t0 = tbl[(size_t)j0 * RECV4 + lane];
        if (lane == 0) {
            float4 pq = tbl[(size_t)j0 * RECV4 + 32];
            p0 += pq.x; p1 += pq.y;
        }
        ax += t0.x; ay += t0.y; az += t0.z; aw += t0.w;
    }
    // reduce psqt partials (live in lanes 0/1) across the warp
    #pragma unroll
    for (int off = 16; off > 0; off >>= 1) {
        p0 += __shfl_xor_sync(FULLM, p0, off);
        p1 += __shfl_xor_sync(FULLM, p1, off);
    }

    // ---- publish partial accumulators (merge BEFORE clip) ----
    reinterpret_cast<float4*>(&s_acc[q][0])[lane] = make_float4(ax, ay, az, aw);
    if (lane == 0) { s_ps[q][0] = p0; s_ps[q][1] = p1; }
    __syncthreads();

    // ---- warp 0 reduces 4 quarters, clips, applies output layer ----
    if (q == 0) {
        float4 a0 = reinterpret_cast<const float4*>(&s_acc[0][0])[lane];
        float4 a1 = reinterpret_cast<const float4*>(&s_acc[1][0])[lane];
        float4 a2 = reinterpret_cast<const float4*>(&s_acc[2][0])[lane];
        float4 a3 = reinterpret_cast<const float4*>(&s_acc[3][0])[lane];
        float rx = a0.x + a1.x + a2.x + a3.x;
        float ry = a0.y + a1.y + a2.y + a3.y;
        float rz = a0.z + a1.z + a2.z + a3.z;
        float rw = a0.w + a1.w + a2.w + a3.w;

        rx = fminf(fmaxf(rx, 0.0f), 1.0f);
        ry = fminf(fmaxf(ry, 0.0f), 1.0f);
        rz = fminf(fmaxf(rz, 0.0f), 1.0f);
        rw = fminf(fmaxf(rw, 0.0f), 1.0f);

        const float4 ow0 = reinterpret_cast<const float4*>(out_w)[lane];
        const float4 ow1 = reinterpret_cast<const float4*>(out_w)[32 + lane];
        float s0 = rx * ow0.x + ry * ow0.y + rz * ow0.z + rw * ow0.w;
        float s1 = rx * ow1.x + ry * ow1.y + rz * ow1.z + rw * ow1.w;
        #pragma unroll
        for (int off = 16; off > 0; off >>= 1) {
            s0 += __shfl_xor_sync(FULLM, s0, off);
            s1 += __shfl_xor_sync(FULLM, s1, off);
        }
        if (lane == 0) {
            float pp0 = s_ps[0][0] + s_ps[1][0] + s_ps[2][0] + s_ps[3][0];
            float pp1 = s_ps[0][1] + s_ps[1][1] + s_ps[2][1] + s_ps[3][1];
            const float sgn = (side == 0) ? 1.0f : -1.0f;
            // each out element receives exactly two adds (+white, -black);
            // fp add is commutative, so the result is order-independent.
            atomicAdd(&out[row * 2 + 0], sgn * (pp0 + s0));
            atomicAdd(&out[row * 2 + 1], sgn * (pp1 + s1));
        }
    }
}

// ---------------------------------------------------------------------------
extern "C" void kernel_launch(void* const* d_in, const int* in_sizes, int n_in,
                              void* d_out, int out_size)
{
    const float* white  = (const float*)d_in[0];
    const float* black  = (const float*)d_in[1];
    const float* psqt_w = (const float*)d_in[2];
    const float* acc_w  = (const float*)d_in[3];
    const float* acc_b  = (const float*)d_in[4];
    const float* out_w  = (const float*)d_in[5];
    (void)in_sizes; (void)n_in; (void)out_size;

    build_table_kernel<<<NF / 32, 256>>>(acc_w, psqt_w, (float*)d_out);

    // PDL launch: builder triggers at entry, so the main kernel co-schedules
    // and streams inputs while the builder writes g_table + zeroes out; the
    // grid sync at the end of phase 1 guarantees visibility of both.
    cudaLaunchConfig_t cfg = {};
    cfg.gridDim  = dim3(BATCH * 2);
    cfg.blockDim = dim3(128);
    cfg.dynamicSmemBytes = 0;
    cfg.stream = 0;
    cudaLaunchAttribute attrs[1];
    attrs[0].id = cudaLaunchAttributeProgrammaticStreamSerialization;
    attrs[0].val.programmaticStreamSerializationAllowed = 1;
    cfg.attrs = attrs;
    cfg.numAttrs = 1;
    cudaLaunchKernelEx(&cfg, nnue_main_kernel,
                       white, black, acc_b, out_w, (float*)d_out);
}